// round 13
// baseline (speedup 1.0000x reference)
#include <cuda_runtime.h>
#include <cuda_bf16.h>
#include <cstdint>
#include <math.h>

#define BDIM 1024
#define DDIM 512
#define CDIM 100000
#define SCALE 64.0f
#define MARGIN 0.35f
#define L2E 1.44269504f
#define TM 64
#define TN 128
#define NT2 ((CDIM + TN - 1) / TN)   // 782 class tiles
#define NBT (BDIM / TM)              // 16 batch tiles

// ---------------- static scratch ---------------------------------------------
__device__ int    g_is64;
__device__ unsigned g_ctr;
__device__ float  g_rnx[BDIM];
__device__ float  g_rwn[CDIM];
__device__ float  g_fx[BDIM];
__device__ float  g_fw[CDIM];
__device__ int8_t g_xq[BDIM * DDIM];
__device__ int8_t g_wq[(size_t)CDIM * DDIM];
__device__ float  g_partial[BDIM * NT2];
__device__ float  g_rowloss[BDIM];

// ---------------- helpers -----------------------------------------------------
__device__ __forceinline__ uint32_t smem_u32(const void* p) {
    uint32_t a;
    asm("{ .reg .u64 t; cvta.to.shared.u64 t, %1; cvt.u32.u64 %0, t; }" : "=r"(a) : "l"(p));
    return a;
}
__device__ __forceinline__ void cpa16(uint32_t dst, const void* src, int pred) {
    int sz = pred ? 16 : 0;
    asm volatile("cp.async.cg.shared.global [%0], [%1], 16, %2;" :: "r"(dst), "l"(src), "r"(sz));
}
#define CP_COMMIT() asm volatile("cp.async.commit_group;" ::: "memory")
#define CP_WAIT1()  asm volatile("cp.async.wait_group 1;" ::: "memory")

#define LDSM4(r0, r1, r2, r3, a) \
    asm volatile("ldmatrix.sync.aligned.m8n8.x4.shared.b16 {%0,%1,%2,%3}, [%4];" \
                 : "=r"(r0), "=r"(r1), "=r"(r2), "=r"(r3) : "r"(a))

#define IMMA16832(d, a, b) \
    asm volatile("mma.sync.aligned.m16n8k32.row.col.s32.s8.s8.s32 " \
                 "{%0,%1,%2,%3}, {%4,%5,%6,%7}, {%8,%9}, {%0,%1,%2,%3};" \
                 : "+r"((d)[0]), "+r"((d)[1]), "+r"((d)[2]), "+r"((d)[3]) \
                 : "r"((a)[0]), "r"((a)[1]), "r"((a)[2]), "r"((a)[3]), "r"((b)[0]), "r"((b)[1]))

__device__ __forceinline__ float ex2(float tt) {
    float r;
    asm("ex2.approx.f32 %0, %1;" : "=f"(r) : "f"(tt));
    return r;
}

// ---------------- label dtype ------------------------------------------------
__device__ __forceinline__ int get_label(const void* p, int i) {
    if (g_is64) return (int)((const long long*)p)[i];
    return ((const int*)p)[i];
}
__global__ void detect_kernel(const void* __restrict__ lab) {
    __shared__ int ok;
    if (threadIdx.x == 0) { ok = 1; g_ctr = 0u; }
    __syncthreads();
    const long long* q = (const long long*)lab;
    for (int i = threadIdx.x; i < BDIM / 2; i += blockDim.x) {
        long long v = q[i];
        if (v < 0 || v >= (long long)CDIM) ok = 0;
    }
    __syncthreads();
    if (threadIdx.x == 0) g_is64 = ok;
}

// ------- normalize + quantize BOTH tensors in one grid ------------------------
__global__ void norm_quant_kernel(const float* __restrict__ input,
                                  const float* __restrict__ weight) {
    int w    = (blockIdx.x * blockDim.x + threadIdx.x) >> 5;
    int lane = threadIdx.x & 31;
    if (w >= BDIM + CDIM) return;
    const int which = (w >= BDIM);
    const int row   = which ? (w - BDIM) : w;
    const float* p  = which ? weight : input;
    const float4* pr = (const float4*)(p + (long long)row * DDIM);
    float4 v[4];
    float ss = 0.f, ma = 0.f;
    #pragma unroll
    for (int j = 0; j < 4; ++j) {
        v[j] = pr[j * 32 + lane];
        ss += v[j].x * v[j].x + v[j].y * v[j].y + v[j].z * v[j].z + v[j].w * v[j].w;
        ma = fmaxf(ma, fmaxf(fmaxf(fabsf(v[j].x), fabsf(v[j].y)),
                             fmaxf(fabsf(v[j].z), fabsf(v[j].w))));
    }
    #pragma unroll
    for (int off = 16; off >= 1; off >>= 1) {
        ss += __shfl_xor_sync(0xffffffffu, ss, off);
        ma = fmaxf(ma, __shfl_xor_sync(0xffffffffu, ma, off));
    }
    float r  = 1.0f / fmaxf(sqrtf(ss), 1e-12f);
    float qs = 127.0f / fmaxf(ma, 1e-30f);
    float f  = ma * r * (1.0f / 127.0f);
    if (lane == 0) {
        if (which) { g_rwn[row] = r; g_fw[row] = f; }
        else       { g_rnx[row] = r; g_fx[row] = f; }
    }
    uint32_t* dst = (uint32_t*)((which ? g_wq : g_xq) + (long long)row * DDIM);
    #pragma unroll
    for (int j = 0; j < 4; ++j) {
        int q0 = __float2int_rn(v[j].x * qs);
        int q1 = __float2int_rn(v[j].y * qs);
        int q2 = __float2int_rn(v[j].z * qs);
        int q3 = __float2int_rn(v[j].w * qs);
        uint32_t pk = (uint32_t)(q0 & 0xff) | ((uint32_t)(q1 & 0xff) << 8) |
                      ((uint32_t)(q2 & 0xff) << 16) | ((uint32_t)(q3 & 0xff) << 24);
        dst[j * 32 + lane] = pk;
    }
}

// smem: stage = A(64*144=9216) + B(128*144=18432) = 27648; 2 stages = 55296
// qx @55296 (256), qw @55552 (512), red @56064 (1024) -> 57088
#define STAGE_BYTES 27648u
#define SM_BOFF 9216u
#define SM_QX  55296
#define SM_QW  55552
#define SM_RED 56064
#define SMEM_TOTAL 57088

// ---------------- hybrid GEMM kernel: IMMA tiles + dp4a tiles -----------------
__global__ __launch_bounds__(256, 2) void tile_kernel() {
    extern __shared__ char smem[];
    const int t    = threadIdx.x;
    const int wid  = t >> 5;
    const int lane = t & 31;
    const int rowBase = blockIdx.x * TM;
    const int colBase = blockIdx.y * TN;
    const uint32_t sb = smem_u32(smem);
    float* qxS = (float*)(smem + SM_QX);
    float* qwS = (float*)(smem + SM_QW);
    float* red = (float*)(smem + SM_RED);
    const bool useDp4a = (blockIdx.y % 7) < 2;   // 224/782 tiles, all full tiles

    if (t < TM) qxS[t] = g_fx[rowBase + t] * (SCALE * L2E);
    if (t >= 128) {
        int c = t - 128;
        int cg = colBase + c;
        qwS[c] = (cg < CDIM) ? g_fw[cg] : 0.f;
    }

    // ---- shared cp.async tile loaders (identical layout both paths) ----
    const int arow = t >> 2;
    const int asec = (t & 3) * 2;
    const int8_t* agp = g_xq + ((long long)(rowBase + arow) << 9) + (asec << 4);
    const uint32_t adst = sb + arow * 144 + asec * 16;

    const int brow = t >> 1;
    const int bsec = (t & 1) * 4;
    int cgB = colBase + brow;
    int bpred = cgB < CDIM;
    const int8_t* bgp = g_wq + ((long long)(bpred ? cgB : 0) << 9) + (bsec << 4);
    const uint32_t bdst = sb + SM_BOFF + brow * 144 + bsec * 16;

    #define LOAD_CHUNK(kc, stg) do {                                        \
        const int8_t* as = agp + ((kc) << 7);                               \
        const int8_t* bs = bgp + ((kc) << 7);                               \
        uint32_t ad = adst + (stg) * STAGE_BYTES;                           \
        uint32_t bd = bdst + (stg) * STAGE_BYTES;                           \
        cpa16(ad,      as,      1);                                         \
        cpa16(ad + 16, as + 16, 1);                                         \
        _Pragma("unroll")                                                   \
        for (int s = 0; s < 4; ++s)                                         \
            cpa16(bd + s * 16, bs + s * 16, bpred);                         \
        CP_COMMIT();                                                        \
    } while (0)

    LOAD_CHUNK(0, 0);
    LOAD_CHUNK(1, 1);

    if (useDp4a) {
        // ======== dp4a path: thread = 8 rows (wid*8..+7) x 4 cols (lane+32j) ====
        int acc[8][4];
        #pragma unroll
        for (int i = 0; i < 8; ++i)
            #pragma unroll
            for (int j = 0; j < 4; ++j) acc[i][j] = 0;

        #pragma unroll 1
        for (int kc = 0; kc < 4; ++kc) {
            const int stg = kc & 1;
            CP_WAIT1();
            __syncthreads();
            const char* aT = smem + stg * STAGE_BYTES + (wid * 8) * 144;
            const char* bT = smem + stg * STAGE_BYTES + SM_BOFF + lane * 144;
            #pragma unroll
            for (int ks = 0; ks < 8; ++ks) {          // 16B k-steps
                uint4 bf[4];
                #pragma unroll
                for (int j = 0; j < 4; ++j)
                    bf[j] = *(const uint4*)(bT + j * 32 * 144 + ks * 16);
                #pragma unroll
                for (int i = 0; i < 8; ++i) {
                    uint4 af = *(const uint4*)(aT + i * 144 + ks * 16);  // broadcast
                    #pragma unroll
                    for (int j = 0; j < 4; ++j) {
                        acc[i][j] = __dp4a((int)af.x, (int)bf[j].x, acc[i][j]);
                        acc[i][j] = __dp4a((int)af.y, (int)bf[j].y, acc[i][j]);
                        acc[i][j] = __dp4a((int)af.z, (int)bf[j].z, acc[i][j]);
                        acc[i][j] = __dp4a((int)af.w, (int)bf[j].w, acc[i][j]);
                    }
                }
            }
            __syncthreads();
            if (kc + 2 < 4) LOAD_CHUNK(kc + 2, stg);
            else CP_COMMIT();
        }
        // epilogue: per-row exp sums, full-warp butterflies, direct g_partial
        float fwv[4];
        #pragma unroll
        for (int j = 0; j < 4; ++j) fwv[j] = qwS[lane + 32 * j];
        #pragma unroll
        for (int i = 0; i < 8; ++i) {
            const int rl = wid * 8 + i;
            const float fxr = qxS[rl];
            float s = 0.f;
            #pragma unroll
            for (int j = 0; j < 4; ++j)
                s += ex2((float)acc[i][j] * (fxr * fwv[j]));
            #pragma unroll
            for (int off = 16; off >= 1; off >>= 1)
                s += __shfl_xor_sync(0xffffffffu, s, off);
            if (lane == 0)
                g_partial[(rowBase + rl) * NT2 + blockIdx.y] = s;
        }
    } else {
        // ======== IMMA path (R10 proven) ========
        const int wm = wid >> 2;
        const int wn = wid & 3;
        const uint32_t aAddrBase = sb + (wm * 32 + (lane & 15)) * 144 + (lane >> 4) * 16;
        const int g = lane >> 3;
        const uint32_t bAddrBase = sb + SM_BOFF
            + (wn * 32 + ((g >> 1) << 3) + (lane & 7)) * 144 + (g & 1) * 16;

        int acc[2][4][4];
        #pragma unroll
        for (int mi = 0; mi < 2; ++mi)
            #pragma unroll
            for (int ni = 0; ni < 4; ++ni)
                #pragma unroll
                for (int c = 0; c < 4; ++c) acc[mi][ni][c] = 0;

        #pragma unroll 1
        for (int kc = 0; kc < 4; ++kc) {
            const int stg = kc & 1;
            CP_WAIT1();
            __syncthreads();
            const uint32_t aB = aAddrBase + stg * STAGE_BYTES;
            const uint32_t bB = bAddrBase + stg * STAGE_BYTES;
            #pragma unroll
            for (int ks = 0; ks < 4; ++ks) {
                uint32_t afr[2][4];
                uint32_t bfr[4][2];
                #pragma unroll
                for (int mi = 0; mi < 2; ++mi)
                    LDSM4(afr[mi][0], afr[mi][1], afr[mi][2], afr[mi][3],
                          aB + mi * 16 * 144 + ks * 32);
                #pragma unroll
                for (int p = 0; p < 2; ++p)
                    LDSM4(bfr[2 * p][0], bfr[2 * p][1], bfr[2 * p + 1][0], bfr[2 * p + 1][1],
                          bB + p * 16 * 144 + ks * 32);
                #pragma unroll
                for (int mi = 0; mi < 2; ++mi)
                    #pragma unroll
                    for (int ni = 0; ni < 4; ++ni)
                        IMMA16832(acc[mi][ni], afr[mi], bfr[ni]);
            }
            __syncthreads();
            if (kc + 2 < 4) LOAD_CHUNK(kc + 2, stg);
            else CP_COMMIT();
        }

        const int groupID = lane >> 2;
        const int tid4    = lane & 3;
        float qwr[8];
        #pragma unroll
        for (int ni = 0; ni < 4; ++ni) {
            qwr[2 * ni]     = qwS[wn * 32 + ni * 8 + tid4 * 2];
            qwr[2 * ni + 1] = qwS[wn * 32 + ni * 8 + tid4 * 2 + 1];
        }
        const bool fullTile = (colBase + TN) <= CDIM;
        #pragma unroll
        for (int mi = 0; mi < 2; ++mi) {
            #pragma unroll
            for (int half = 0; half < 2; ++half) {
                const int rl  = wm * 32 + mi * 16 + groupID + half * 8;
                const float fxr = qxS[rl];
                float fq[8];
                #pragma unroll
                for (int c = 0; c < 8; ++c) fq[c] = fxr * qwr[c];
                float s0 = 0.f, s1 = 0.f;
                if (fullTile) {
                    #pragma unroll
                    for (int ni = 0; ni < 4; ++ni) {
                        float fa0 = (float)acc[mi][ni][half * 2 + 0];
                        float fa1 = (float)acc[mi][ni][half * 2 + 1];
                        s0 += ex2(fa0 * fq[2 * ni]);
                        s1 += ex2(fa1 * fq[2 * ni + 1]);
                    }
                } else {
                    #pragma unroll
                    for (int ni = 0; ni < 4; ++ni) {
                        #pragma unroll
                        for (int cc = 0; cc < 2; ++cc) {
                            const int col = colBase + wn * 32 + ni * 8 + tid4 * 2 + cc;
                            if (col < CDIM) {
                                float fa = (float)acc[mi][ni][half * 2 + cc];
                                s0 += ex2(fa * fq[2 * ni + cc]);
                            }
                        }
                    }
                }
                float s = s0 + s1;
                s += __shfl_xor_sync(0xffffffffu, s, 1);
                s += __shfl_xor_sync(0xffffffffu, s, 2);
                if (tid4 == 0) red[rl * 4 + wn] = s;
            }
        }
        __syncthreads();
        if (t < TM) {
            float s = red[t * 4 + 0] + red[t * 4 + 1] + red[t * 4 + 2] + red[t * 4 + 3];
            g_partial[(rowBase + t) * NT2 + blockIdx.y] = s;
        }
    }
}

// ------- fused per-row: target dot + margin fixup + logsumexp + loss + mean ---
__global__ void row_kernel(const float* __restrict__ input,
                           const void*  __restrict__ label,
                           const float* __restrict__ weight,
                           float* __restrict__ out) {
    __shared__ float smf[4];
    __shared__ int   smi[4];
    __shared__ float smp[4];
    __shared__ int   isLast;
    const int r    = blockIdx.x;
    const int t    = threadIdx.x;
    const int lane = t & 31;
    const int wd   = t >> 5;
    const int lab  = get_label(label, r);

    const float4* xr = (const float4*)(input  + (long long)r   * DDIM);
    const float4* wr = (const float4*)(weight + (long long)lab * DDIM);
    float4 a = xr[t], b = wr[t];
    float s  = a.x * b.x + a.y * b.y + a.z * b.z + a.w * b.w;
    int   id = __dp4a(((const int*)(g_xq + ((long long)r   << 9)))[t],
                      ((const int*)(g_wq + ((long long)lab << 9)))[t], 0);
    float ps = 0.f;
    const float* pp = g_partial + (long long)r * NT2;
    for (int i = t; i < NT2; i += 128) ps += pp[i];

    #pragma unroll
    for (int off = 16; off >= 1; off >>= 1) {
        s  += __shfl_xor_sync(0xffffffffu, s, off);
        id += __shfl_xor_sync(0xffffffffu, id, off);
        ps += __shfl_xor_sync(0xffffffffu, ps, off);
    }
    if (lane == 0) { smf[wd] = s; smi[wd] = id; smp[wd] = ps; }
    __syncthreads();
    if (t == 0) {
        float st = smf[0] + smf[1] + smf[2] + smf[3];
        int   it = smi[0] + smi[1] + smi[2] + smi[3];
        float pt = smp[0] + smp[1] + smp[2] + smp[3];
        float tgt = SCALE * (st * g_rnx[r] * g_rwn[lab] - MARGIN);
        float fxr = g_fx[r] * (SCALE * L2E);
        float fq  = fxr * g_fw[lab];
        float tt  = (float)it * fq;
        float fix = ex2(tt - (SCALE * MARGIN * L2E)) - ex2(tt);
        g_rowloss[r] = logf(pt + fix) - tgt;
        __threadfence();
        unsigned v = atomicAdd(&g_ctr, 1u);
        isLast = (v == (unsigned)(BDIM - 1));
    }
    __syncthreads();
    if (isLast) {
        float v = g_rowloss[t] + g_rowloss[t + 128] + g_rowloss[t + 256] +
                  g_rowloss[t + 384] + g_rowloss[t + 512] + g_rowloss[t + 640] +
                  g_rowloss[t + 768] + g_rowloss[t + 896];
        #pragma unroll
        for (int off = 16; off >= 1; off >>= 1)
            v += __shfl_xor_sync(0xffffffffu, v, off);
        if (lane == 0) smf[wd] = v;
        __syncthreads();
        if (t == 0)
            out[0] = (smf[0] + smf[1] + smf[2] + smf[3]) * (1.0f / (float)BDIM);
    }
}

// ---------------- launch ------------------------------------------------------
extern "C" void kernel_launch(void* const* d_in, const int* in_sizes, int n_in,
                              void* d_out, int out_size) {
    const float* input  = (const float*)d_in[0];
    const void*  label  = d_in[1];
    const float* weight = (const float*)d_in[2];
    float* out = (float*)d_out;

    cudaFuncSetAttribute(tile_kernel, cudaFuncAttributeMaxDynamicSharedMemorySize, SMEM_TOTAL);

    detect_kernel<<<1, 256>>>(label);
    norm_quant_kernel<<<((BDIM + CDIM) * 32 + 255) / 256, 256>>>(input, weight);

    dim3 grid(NBT, NT2);
    tile_kernel<<<grid, 256, SMEM_TOTAL>>>();

    row_kernel<<<BDIM, 128>>>(input, label, weight, out);
}

// round 15
// speedup vs baseline: 1.9675x; 1.9675x over previous
#include <cuda_runtime.h>
#include <cuda_bf16.h>
#include <cstdint>
#include <math.h>

#define BDIM 1024
#define DDIM 512
#define CDIM 100000
#define SCALE 64.0f
#define MARGIN 0.35f
#define L2E 1.44269504f
#define TM 64
#define TN 128
#define NT2 ((CDIM + TN - 1) / TN)   // 782 class tiles
#define NRG 4                        // row groups (256 rows each)

// ---------------- static scratch ---------------------------------------------
__device__ int    g_is64;
__device__ unsigned g_ctr;
__device__ float  g_rnx[BDIM];
__device__ float  g_rwn[CDIM];
__device__ float  g_fx[BDIM];
__device__ float  g_fw[CDIM];
__device__ int8_t g_xq[BDIM * DDIM];
__device__ int8_t g_wq[(size_t)CDIM * DDIM];
__device__ float  g_partial[BDIM * NT2];
__device__ float  g_rowloss[BDIM];

// ---------------- helpers -----------------------------------------------------
__device__ __forceinline__ uint32_t smem_u32(const void* p) {
    uint32_t a;
    asm("{ .reg .u64 t; cvta.to.shared.u64 t, %1; cvt.u32.u64 %0, t; }" : "=r"(a) : "l"(p));
    return a;
}
__device__ __forceinline__ void cpa16(uint32_t dst, const void* src, int pred) {
    int sz = pred ? 16 : 0;
    asm volatile("cp.async.cg.shared.global [%0], [%1], 16, %2;" :: "r"(dst), "l"(src), "r"(sz));
}
#define CP_COMMIT() asm volatile("cp.async.commit_group;" ::: "memory")
#define CP_WAIT1()  asm volatile("cp.async.wait_group 1;" ::: "memory")
#define CP_WAIT0()  asm volatile("cp.async.wait_group 0;" ::: "memory")

#define LDSM4(r0, r1, r2, r3, a) \
    asm volatile("ldmatrix.sync.aligned.m8n8.x4.shared.b16 {%0,%1,%2,%3}, [%4];" \
                 : "=r"(r0), "=r"(r1), "=r"(r2), "=r"(r3) : "r"(a))

#define IMMA16832(d, a, b) \
    asm volatile("mma.sync.aligned.m16n8k32.row.col.s32.s8.s8.s32 " \
                 "{%0,%1,%2,%3}, {%4,%5,%6,%7}, {%8,%9}, {%0,%1,%2,%3};" \
                 : "+r"((d)[0]), "+r"((d)[1]), "+r"((d)[2]), "+r"((d)[3]) \
                 : "r"((a)[0]), "r"((a)[1]), "r"((a)[2]), "r"((a)[3]), "r"((b)[0]), "r"((b)[1]))

__device__ __forceinline__ float ex2(float tt) {
    float r;
    asm("ex2.approx.f32 %0, %1;" : "=f"(r) : "f"(tt));
    return r;
}

// ---------------- label dtype ------------------------------------------------
__device__ __forceinline__ int get_label(const void* p, int i) {
    if (g_is64) return (int)((const long long*)p)[i];
    return ((const int*)p)[i];
}
__global__ void detect_kernel(const void* __restrict__ lab) {
    __shared__ int ok;
    if (threadIdx.x == 0) { ok = 1; g_ctr = 0u; }
    __syncthreads();
    const long long* q = (const long long*)lab;
    for (int i = threadIdx.x; i < BDIM / 2; i += blockDim.x) {
        long long v = q[i];
        if (v < 0 || v >= (long long)CDIM) ok = 0;
    }
    __syncthreads();
    if (threadIdx.x == 0) g_is64 = ok;
}

// ------- normalize + quantize BOTH tensors in one grid ------------------------
__global__ void norm_quant_kernel(const float* __restrict__ input,
                                  const float* __restrict__ weight) {
    int w    = (blockIdx.x * blockDim.x + threadIdx.x) >> 5;
    int lane = threadIdx.x & 31;
    if (w >= BDIM + CDIM) return;
    const int which = (w >= BDIM);
    const int row   = which ? (w - BDIM) : w;
    const float* p  = which ? weight : input;
    const float4* pr = (const float4*)(p + (long long)row * DDIM);
    float4 v[4];
    float ss = 0.f, ma = 0.f;
    #pragma unroll
    for (int j = 0; j < 4; ++j) {
        v[j] = pr[j * 32 + lane];
        ss += v[j].x * v[j].x + v[j].y * v[j].y + v[j].z * v[j].z + v[j].w * v[j].w;
        ma = fmaxf(ma, fmaxf(fmaxf(fabsf(v[j].x), fabsf(v[j].y)),
                             fmaxf(fabsf(v[j].z), fabsf(v[j].w))));
    }
    #pragma unroll
    for (int off = 16; off >= 1; off >>= 1) {
        ss += __shfl_xor_sync(0xffffffffu, ss, off);
        ma = fmaxf(ma, __shfl_xor_sync(0xffffffffu, ma, off));
    }
    float r  = 1.0f / fmaxf(sqrtf(ss), 1e-12f);
    float qs = 127.0f / fmaxf(ma, 1e-30f);
    float f  = ma * r * (1.0f / 127.0f);
    if (lane == 0) {
        if (which) { g_rwn[row] = r; g_fw[row] = f; }
        else       { g_rnx[row] = r; g_fx[row] = f; }
    }
    uint32_t* dst = (uint32_t*)((which ? g_wq : g_xq) + (long long)row * DDIM);
    #pragma unroll
    for (int j = 0; j < 4; ++j) {
        int q0 = __float2int_rn(v[j].x * qs);
        int q1 = __float2int_rn(v[j].y * qs);
        int q2 = __float2int_rn(v[j].z * qs);
        int q3 = __float2int_rn(v[j].w * qs);
        uint32_t pk = (uint32_t)(q0 & 0xff) | ((uint32_t)(q1 & 0xff) << 8) |
                      ((uint32_t)(q2 & 0xff) << 16) | ((uint32_t)(q3 & 0xff) << 24);
        dst[j * 32 + lane] = pk;
    }
}

// smem layout:
//   B: 4 chunk regions @ 0,     each 128 rows x 144 B = 18432  -> 73728
//   A: 4 slots         @ 73728, each 64 rows x 144 B  = 9216   -> 36864
//   qx @110592 (256 floats), qw @111616 (128 floats), red @112128 (1024 B)
#define SM_A    73728u
#define SM_QX   110592
#define SM_QW   111616
#define SM_RED  112128
#define SMEM_TOTAL 113152

// ---------------- B-resident multi-row-tile IMMA kernel -----------------------
// grid = (NRG, NT2): block loads B[colTile] for full K once, loops 4 row tiles.
__global__ __launch_bounds__(256, 2) void tile_kernel() {
    extern __shared__ char smem[];
    const int t    = threadIdx.x;
    const int wid  = t >> 5;
    const int lane = t & 31;
    const int wm   = wid >> 2;
    const int wn   = wid & 3;
    const int rgBase  = blockIdx.x * 256;       // first row of this row group
    const int colBase = blockIdx.y * TN;
    const uint32_t sb = smem_u32(smem);
    float* qxS = (float*)(smem + SM_QX);
    float* qwS = (float*)(smem + SM_QW);
    float* red = (float*)(smem + SM_RED);

    qxS[t] = g_fx[rgBase + t] * (SCALE * L2E);
    if (t < TN) {
        int cg = colBase + t;
        qwS[t] = (cg < CDIM) ? g_fw[cg] : 0.f;
    }

    // ---- B loader: all 4 K-chunks, one commit group (64 KB) ----
    const int brow = t >> 1;
    const int bsec = (t & 1) * 4;
    int cgB = colBase + brow;
    int bpred = cgB < CDIM;
    const int8_t* bgp = g_wq + ((long long)(bpred ? cgB : 0) << 9) + (bsec << 4);
    const uint32_t bdst = sb + brow * 144 + bsec * 16;
    #pragma unroll
    for (int c = 0; c < 4; ++c) {
        #pragma unroll
        for (int s = 0; s < 4; ++s)
            cpa16(bdst + c * 18432u + s * 16, bgp + (c << 7) + s * 16, bpred);
    }
    CP_COMMIT();

    // ---- A loader (tile i: r = i>>2, kc = i&3; slot = i&3 of 4) ----
    const int arow = t >> 2;
    const int asec = (t & 3) * 2;
    const uint32_t adst0 = sb + SM_A + arow * 144 + asec * 16;
    #define LOAD_A(i) do {                                                     \
        int r_ = (i) >> 2, kc_ = (i) & 3;                                      \
        const int8_t* as = g_xq + ((long long)(rgBase + r_ * 64 + arow) << 9)  \
                           + (kc_ << 7) + (asec << 4);                         \
        uint32_t ad = adst0 + (uint32_t)((i) & 3) * 9216u;                     \
        cpa16(ad,      as,      1);                                            \
        cpa16(ad + 16, as + 16, 1);                                            \
        CP_COMMIT();                                                           \
    } while (0)

    LOAD_A(0);
    LOAD_A(1);

    // BARRIER: qxS/qwS written above by subsets of threads; qwr below is read
    // by ALL warps. (Missing barrier here was the R14 NaN bug.)
    __syncthreads();

    const uint32_t aAddrBase = sb + SM_A + (wm * 32 + (lane & 15)) * 144 + (lane >> 4) * 16;
    const int g = lane >> 3;
    const uint32_t bAddrBase = sb
        + (wn * 32 + ((g >> 1) << 3) + (lane & 7)) * 144 + (g & 1) * 16;

    const bool fullTile = (colBase + TN) <= CDIM;
    const int groupID = lane >> 2;
    const int tid4    = lane & 3;
    float qwr[8];
    #pragma unroll
    for (int ni = 0; ni < 4; ++ni) {
        qwr[2 * ni]     = qwS[wn * 32 + ni * 8 + tid4 * 2];
        qwr[2 * ni + 1] = qwS[wn * 32 + ni * 8 + tid4 * 2 + 1];
    }

    int acc[2][4][4];
    #pragma unroll
    for (int mi = 0; mi < 2; ++mi)
        #pragma unroll
        for (int ni = 0; ni < 4; ++ni)
            #pragma unroll
            for (int c = 0; c < 4; ++c) acc[mi][ni][c] = 0;

    #pragma unroll 1
    for (int i = 0; i < 16; ++i) {
        // pipeline: depth-2 A prefetch over resident B
        if (i < 14) {
            CP_WAIT1();
            __syncthreads();
            LOAD_A(i + 2);
        } else if (i == 14) {
            CP_WAIT1();
            __syncthreads();
        } else {
            CP_WAIT0();
            __syncthreads();
        }
        const uint32_t aB = aAddrBase + (uint32_t)(i & 3) * 9216u;
        const uint32_t bB = bAddrBase + (uint32_t)(i & 3) * 18432u;
        #pragma unroll
        for (int ks = 0; ks < 4; ++ks) {
            uint32_t afr[2][4];
            uint32_t bfr[4][2];
            #pragma unroll
            for (int mi = 0; mi < 2; ++mi)
                LDSM4(afr[mi][0], afr[mi][1], afr[mi][2], afr[mi][3],
                      aB + mi * 16 * 144 + ks * 32);
            #pragma unroll
            for (int p = 0; p < 2; ++p)
                LDSM4(bfr[2 * p][0], bfr[2 * p][1], bfr[2 * p + 1][0], bfr[2 * p + 1][1],
                      bB + p * 16 * 144 + ks * 32);
            #pragma unroll
            for (int mi = 0; mi < 2; ++mi)
                #pragma unroll
                for (int ni = 0; ni < 4; ++ni)
                    IMMA16832(acc[mi][ni], afr[mi], bfr[ni]);
        }

        if ((i & 3) == 3) {
            // ---- epilogue for row tile r = i>>2 ----
            const int r_ = i >> 2;
            #pragma unroll
            for (int mi = 0; mi < 2; ++mi) {
                #pragma unroll
                for (int half = 0; half < 2; ++half) {
                    const int rl  = wm * 32 + mi * 16 + groupID + half * 8;
                    const float fxr = qxS[r_ * 64 + rl];
                    float fq[8];
                    #pragma unroll
                    for (int c = 0; c < 8; ++c) fq[c] = fxr * qwr[c];
                    float s0 = 0.f, s1 = 0.f;
                    if (fullTile) {
                        #pragma unroll
                        for (int ni = 0; ni < 4; ++ni) {
                            float fa0 = (float)acc[mi][ni][half * 2 + 0];
                            float fa1 = (float)acc[mi][ni][half * 2 + 1];
                            s0 += ex2(fa0 * fq[2 * ni]);
                            s1 += ex2(fa1 * fq[2 * ni + 1]);
                        }
                    } else {
                        #pragma unroll
                        for (int ni = 0; ni < 4; ++ni) {
                            #pragma unroll
                            for (int cc = 0; cc < 2; ++cc) {
                                const int col = colBase + wn * 32 + ni * 8 + tid4 * 2 + cc;
                                if (col < CDIM) {
                                    float fa = (float)acc[mi][ni][half * 2 + cc];
                                    s0 += ex2(fa * fq[2 * ni + cc]);
                                }
                            }
                        }
                    }
                    float s = s0 + s1;
                    s += __shfl_xor_sync(0xffffffffu, s, 1);
                    s += __shfl_xor_sync(0xffffffffu, s, 2);
                    if (tid4 == 0) red[rl * 4 + wn] = s;
                }
            }
            __syncthreads();
            if (t < TM) {
                float s = red[t * 4 + 0] + red[t * 4 + 1] + red[t * 4 + 2] + red[t * 4 + 3];
                g_partial[(rgBase + r_ * 64 + t) * NT2 + blockIdx.y] = s;
            }
            // reset accumulators for next row tile
            #pragma unroll
            for (int mi = 0; mi < 2; ++mi)
                #pragma unroll
                for (int ni = 0; ni < 4; ++ni)
                    #pragma unroll
                    for (int c = 0; c < 4; ++c) acc[mi][ni][c] = 0;
        }
    }
}

// ------- fused per-row: target dot + margin fixup + logsumexp + loss + mean ---
__global__ void row_kernel(const float* __restrict__ input,
                           const void*  __restrict__ label,
                           const float* __restrict__ weight,
                           float* __restrict__ out) {
    __shared__ float smf[4];
    __shared__ int   smi[4];
    __shared__ float smp[4];
    __shared__ int   isLast;
    const int r    = blockIdx.x;
    const int t    = threadIdx.x;
    const int lane = t & 31;
    const int wd   = t >> 5;
    const int lab  = get_label(label, r);

    const float4* xr = (const float4*)(input  + (long long)r   * DDIM);
    const float4* wr = (const float4*)(weight + (long long)lab * DDIM);
    float4 a = xr[t], b = wr[t];
    float s  = a.x * b.x + a.y * b.y + a.z * b.z + a.w * b.w;
    int   id = __dp4a(((const int*)(g_xq + ((long long)r   << 9)))[t],
                      ((const int*)(g_wq + ((long long)lab << 9)))[t], 0);
    float ps = 0.f;
    const float* pp = g_partial + (long long)r * NT2;
    for (int i = t; i < NT2; i += 128) ps += pp[i];

    #pragma unroll
    for (int off = 16; off >= 1; off >>= 1) {
        s  += __shfl_xor_sync(0xffffffffu, s, off);
        id += __shfl_xor_sync(0xffffffffu, id, off);
        ps += __shfl_xor_sync(0xffffffffu, ps, off);
    }
    if (lane == 0) { smf[wd] = s; smi[wd] = id; smp[wd] = ps; }
    __syncthreads();
    if (t == 0) {
        float st = smf[0] + smf[1] + smf[2] + smf[3];
        int   it = smi[0] + smi[1] + smi[2] + smi[3];
        float pt = smp[0] + smp[1] + smp[2] + smp[3];
        float tgt = SCALE * (st * g_rnx[r] * g_rwn[lab] - MARGIN);
        float fxr = g_fx[r] * (SCALE * L2E);
        float fq  = fxr * g_fw[lab];
        float tt  = (float)it * fq;
        float fix = ex2(tt - (SCALE * MARGIN * L2E)) - ex2(tt);
        g_rowloss[r] = logf(pt + fix) - tgt;
        __threadfence();
        unsigned v = atomicAdd(&g_ctr, 1u);
        isLast = (v == (unsigned)(BDIM - 1));
    }
    __syncthreads();
    if (isLast) {
        float v = g_rowloss[t] + g_rowloss[t + 128] + g_rowloss[t + 256] +
                  g_rowloss[t + 384] + g_rowloss[t + 512] + g_rowloss[t + 640] +
                  g_rowloss[t + 768] + g_rowloss[t + 896];
        #pragma unroll
        for (int off = 16; off >= 1; off >>= 1)
            v += __shfl_xor_sync(0xffffffffu, v, off);
        if (lane == 0) smf[wd] = v;
        __syncthreads();
        if (t == 0)
            out[0] = (smf[0] + smf[1] + smf[2] + smf[3]) * (1.0f / (float)BDIM);
    }
}

// ---------------- launch ------------------------------------------------------
extern "C" void kernel_launch(void* const* d_in, const int* in_sizes, int n_in,
                              void* d_out, int out_size) {
    const float* input  = (const float*)d_in[0];
    const void*  label  = d_in[1];
    const float* weight = (const float*)d_in[2];
    float* out = (float*)d_out;

    cudaFuncSetAttribute(tile_kernel, cudaFuncAttributeMaxDynamicSharedMemorySize, SMEM_TOTAL);

    detect_kernel<<<1, 256>>>(label);
    norm_quant_kernel<<<((BDIM + CDIM) * 32 + 255) / 256, 256>>>(input, weight);

    dim3 grid(NRG, NT2);
    tile_kernel<<<grid, 256, SMEM_TOTAL>>>();

    row_kernel<<<BDIM, 128>>>(input, label, weight, out);
}

// round 16
// speedup vs baseline: 1.9684x; 1.0005x over previous
#include <cuda_runtime.h>
#include <cuda_bf16.h>
#include <cstdint>
#include <math.h>

#define BDIM 1024
#define DDIM 512
#define CDIM 100000
#define SCALE 64.0f
#define MARGIN 0.35f
#define L2E 1.44269504f
#define TM 64
#define TN 128
#define NT2 ((CDIM + TN - 1) / TN)   // 782 class tiles
#define NRG 4                        // row groups (256 rows each)

// ---------------- static scratch ---------------------------------------------
__device__ int    g_is64;
__device__ unsigned g_ctr;
__device__ float  g_rnx[BDIM];
__device__ float  g_rwn[CDIM];
__device__ float  g_fx[BDIM];
__device__ float  g_fw[CDIM];
__device__ int8_t g_xq[BDIM * DDIM];
__device__ int8_t g_wq[(size_t)CDIM * DDIM];
__device__ float  g_partial[BDIM * NT2];
__device__ float  g_rowloss[BDIM];

// ---------------- helpers -----------------------------------------------------
__device__ __forceinline__ uint32_t smem_u32(const void* p) {
    uint32_t a;
    asm("{ .reg .u64 t; cvta.to.shared.u64 t, %1; cvt.u32.u64 %0, t; }" : "=r"(a) : "l"(p));
    return a;
}
__device__ __forceinline__ void cpa16(uint32_t dst, const void* src, int pred) {
    int sz = pred ? 16 : 0;
    asm volatile("cp.async.cg.shared.global [%0], [%1], 16, %2;" :: "r"(dst), "l"(src), "r"(sz));
}
#define CP_COMMIT() asm volatile("cp.async.commit_group;" ::: "memory")
#define CP_WAIT1()  asm volatile("cp.async.wait_group 1;" ::: "memory")
#define CP_WAIT0()  asm volatile("cp.async.wait_group 0;" ::: "memory")

#define LDSM4(r0, r1, r2, r3, a) \
    asm volatile("ldmatrix.sync.aligned.m8n8.x4.shared.b16 {%0,%1,%2,%3}, [%4];" \
                 : "=r"(r0), "=r"(r1), "=r"(r2), "=r"(r3) : "r"(a))

#define IMMA16832(d, a, b) \
    asm volatile("mma.sync.aligned.m16n8k32.row.col.s32.s8.s8.s32 " \
                 "{%0,%1,%2,%3}, {%4,%5,%6,%7}, {%8,%9}, {%0,%1,%2,%3};" \
                 : "+r"((d)[0]), "+r"((d)[1]), "+r"((d)[2]), "+r"((d)[3]) \
                 : "r"((a)[0]), "r"((a)[1]), "r"((a)[2]), "r"((a)[3]), "r"((b)[0]), "r"((b)[1]))

__device__ __forceinline__ float ex2(float tt) {
    float r;
    asm("ex2.approx.f32 %0, %1;" : "=f"(r) : "f"(tt));
    return r;
}

// ---------------- label dtype ------------------------------------------------
__device__ __forceinline__ int get_label(const void* p, int i) {
    if (g_is64) return (int)((const long long*)p)[i];
    return ((const int*)p)[i];
}
__global__ void detect_kernel(const void* __restrict__ lab) {
    __shared__ int ok;
    if (threadIdx.x == 0) { ok = 1; g_ctr = 0u; }
    __syncthreads();
    const long long* q = (const long long*)lab;
    for (int i = threadIdx.x; i < BDIM / 2; i += blockDim.x) {
        long long v = q[i];
        if (v < 0 || v >= (long long)CDIM) ok = 0;
    }
    __syncthreads();
    if (threadIdx.x == 0) g_is64 = ok;
}

// ------- normalize + quantize BOTH tensors in one grid ------------------------
__global__ void norm_quant_kernel(const float* __restrict__ input,
                                  const float* __restrict__ weight) {
    int w    = (blockIdx.x * blockDim.x + threadIdx.x) >> 5;
    int lane = threadIdx.x & 31;
    if (w >= BDIM + CDIM) return;
    const int which = (w >= BDIM);
    const int row   = which ? (w - BDIM) : w;
    const float* p  = which ? weight : input;
    const float4* pr = (const float4*)(p + (long long)row * DDIM);
    float4 v[4];
    float ss = 0.f, ma = 0.f;
    #pragma unroll
    for (int j = 0; j < 4; ++j) {
        v[j] = pr[j * 32 + lane];
        ss += v[j].x * v[j].x + v[j].y * v[j].y + v[j].z * v[j].z + v[j].w * v[j].w;
        ma = fmaxf(ma, fmaxf(fmaxf(fabsf(v[j].x), fabsf(v[j].y)),
                             fmaxf(fabsf(v[j].z), fabsf(v[j].w))));
    }
    #pragma unroll
    for (int off = 16; off >= 1; off >>= 1) {
        ss += __shfl_xor_sync(0xffffffffu, ss, off);
        ma = fmaxf(ma, __shfl_xor_sync(0xffffffffu, ma, off));
    }
    float r  = 1.0f / fmaxf(sqrtf(ss), 1e-12f);
    float qs = 127.0f / fmaxf(ma, 1e-30f);
    float f  = ma * r * (1.0f / 127.0f);
    if (lane == 0) {
        if (which) { g_rwn[row] = r; g_fw[row] = f; }
        else       { g_rnx[row] = r; g_fx[row] = f; }
    }
    uint32_t* dst = (uint32_t*)((which ? g_wq : g_xq) + (long long)row * DDIM);
    #pragma unroll
    for (int j = 0; j < 4; ++j) {
        int q0 = __float2int_rn(v[j].x * qs);
        int q1 = __float2int_rn(v[j].y * qs);
        int q2 = __float2int_rn(v[j].z * qs);
        int q3 = __float2int_rn(v[j].w * qs);
        uint32_t pk = (uint32_t)(q0 & 0xff) | ((uint32_t)(q1 & 0xff) << 8) |
                      ((uint32_t)(q2 & 0xff) << 16) | ((uint32_t)(q3 & 0xff) << 24);
        dst[j * 32 + lane] = pk;
    }
}

// smem layout:
//   B: 4 chunk regions @ 0,     each 128 rows x 144 B = 18432  -> 73728
//   A: 4 slots         @ 73728, each 64 rows x 144 B  = 9216   -> 36864
//   qx @110592 (256 floats), qw @111616 (128 floats), red @112128 (1024 B)
#define SM_A    73728u
#define SM_QX   110592
#define SM_QW   111616
#define SM_RED  112128
#define SMEM_TOTAL 113152

// ---------------- B-resident multi-row-tile IMMA kernel -----------------------
// grid = (NRG, NT2): block loads B[colTile] for full K once, loops 4 row tiles.
__global__ __launch_bounds__(256, 2) void tile_kernel() {
    extern __shared__ char smem[];
    const int t    = threadIdx.x;
    const int wid  = t >> 5;
    const int lane = t & 31;
    const int wm   = wid >> 2;
    const int wn   = wid & 3;
    const int rgBase  = blockIdx.x * 256;       // first row of this row group
    const int colBase = blockIdx.y * TN;
    const uint32_t sb = smem_u32(smem);
    float* qxS = (float*)(smem + SM_QX);
    float* qwS = (float*)(smem + SM_QW);
    float* red = (float*)(smem + SM_RED);

    qxS[t] = g_fx[rgBase + t] * (SCALE * L2E);
    if (t < TN) {
        int cg = colBase + t;
        qwS[t] = (cg < CDIM) ? g_fw[cg] : 0.f;
    }

    // ---- B loader: all 4 K-chunks, one commit group (64 KB) ----
    const int brow = t >> 1;
    const int bsec = (t & 1) * 4;
    int cgB = colBase + brow;
    int bpred = cgB < CDIM;
    const int8_t* bgp = g_wq + ((long long)(bpred ? cgB : 0) << 9) + (bsec << 4);
    const uint32_t bdst = sb + brow * 144 + bsec * 16;
    #pragma unroll
    for (int c = 0; c < 4; ++c) {
        #pragma unroll
        for (int s = 0; s < 4; ++s)
            cpa16(bdst + c * 18432u + s * 16, bgp + (c << 7) + s * 16, bpred);
    }
    CP_COMMIT();

    // ---- A loader (tile i: r = i>>2, kc = i&3; slot = i&3 of 4) ----
    const int arow = t >> 2;
    const int asec = (t & 3) * 2;
    const uint32_t adst0 = sb + SM_A + arow * 144 + asec * 16;
    #define LOAD_A(i) do {                                                     \
        int r_ = (i) >> 2, kc_ = (i) & 3;                                      \
        const int8_t* as = g_xq + ((long long)(rgBase + r_ * 64 + arow) << 9)  \
                           + (kc_ << 7) + (asec << 4);                         \
        uint32_t ad = adst0 + (uint32_t)((i) & 3) * 9216u;                     \
        cpa16(ad,      as,      1);                                            \
        cpa16(ad + 16, as + 16, 1);                                            \
        CP_COMMIT();                                                           \
    } while (0)

    LOAD_A(0);
    LOAD_A(1);

    // BARRIER: qxS/qwS written above by subsets of threads; qwr below is read
    // by ALL warps. (Missing barrier here was the R14 NaN bug.)
    __syncthreads();

    const uint32_t aAddrBase = sb + SM_A + (wm * 32 + (lane & 15)) * 144 + (lane >> 4) * 16;
    const int g = lane >> 3;
    const uint32_t bAddrBase = sb
        + (wn * 32 + ((g >> 1) << 3) + (lane & 7)) * 144 + (g & 1) * 16;

    const bool fullTile = (colBase + TN) <= CDIM;
    const int groupID = lane >> 2;
    const int tid4    = lane & 3;
    float qwr[8];
    #pragma unroll
    for (int ni = 0; ni < 4; ++ni) {
        qwr[2 * ni]     = qwS[wn * 32 + ni * 8 + tid4 * 2];
        qwr[2 * ni + 1] = qwS[wn * 32 + ni * 8 + tid4 * 2 + 1];
    }

    int acc[2][4][4];
    #pragma unroll
    for (int mi = 0; mi < 2; ++mi)
        #pragma unroll
        for (int ni = 0; ni < 4; ++ni)
            #pragma unroll
            for (int c = 0; c < 4; ++c) acc[mi][ni][c] = 0;

    #pragma unroll 1
    for (int i = 0; i < 16; ++i) {
        // pipeline: depth-2 A prefetch over resident B
        if (i < 14) {
            CP_WAIT1();
            __syncthreads();
            LOAD_A(i + 2);
        } else if (i == 14) {
            CP_WAIT1();
            __syncthreads();
        } else {
            CP_WAIT0();
            __syncthreads();
        }
        const uint32_t aB = aAddrBase + (uint32_t)(i & 3) * 9216u;
        const uint32_t bB = bAddrBase + (uint32_t)(i & 3) * 18432u;
        #pragma unroll
        for (int ks = 0; ks < 4; ++ks) {
            uint32_t afr[2][4];
            uint32_t bfr[4][2];
            #pragma unroll
            for (int mi = 0; mi < 2; ++mi)
                LDSM4(afr[mi][0], afr[mi][1], afr[mi][2], afr[mi][3],
                      aB + mi * 16 * 144 + ks * 32);
            #pragma unroll
            for (int p = 0; p < 2; ++p)
                LDSM4(bfr[2 * p][0], bfr[2 * p][1], bfr[2 * p + 1][0], bfr[2 * p + 1][1],
                      bB + p * 16 * 144 + ks * 32);
            #pragma unroll
            for (int mi = 0; mi < 2; ++mi)
                #pragma unroll
                for (int ni = 0; ni < 4; ++ni)
                    IMMA16832(acc[mi][ni], afr[mi], bfr[ni]);
        }

        if ((i & 3) == 3) {
            // ---- epilogue for row tile r = i>>2 ----
            const int r_ = i >> 2;
            #pragma unroll
            for (int mi = 0; mi < 2; ++mi) {
                #pragma unroll
                for (int half = 0; half < 2; ++half) {
                    const int rl  = wm * 32 + mi * 16 + groupID + half * 8;
                    const float fxr = qxS[r_ * 64 + rl];
                    float fq[8];
                    #pragma unroll
                    for (int c = 0; c < 8; ++c) fq[c] = fxr * qwr[c];
                    float s0 = 0.f, s1 = 0.f;
                    if (fullTile) {
                        #pragma unroll
                        for (int ni = 0; ni < 4; ++ni) {
                            float fa0 = (float)acc[mi][ni][half * 2 + 0];
                            float fa1 = (float)acc[mi][ni][half * 2 + 1];
                            s0 += ex2(fa0 * fq[2 * ni]);
                            s1 += ex2(fa1 * fq[2 * ni + 1]);
                        }
                    } else {
                        #pragma unroll
                        for (int ni = 0; ni < 4; ++ni) {
                            #pragma unroll
                            for (int cc = 0; cc < 2; ++cc) {
                                const int col = colBase + wn * 32 + ni * 8 + tid4 * 2 + cc;
                                if (col < CDIM) {
                                    float fa = (float)acc[mi][ni][half * 2 + cc];
                                    s0 += ex2(fa * fq[2 * ni + cc]);
                                }
                            }
                        }
                    }
                    float s = s0 + s1;
                    s += __shfl_xor_sync(0xffffffffu, s, 1);
                    s += __shfl_xor_sync(0xffffffffu, s, 2);
                    if (tid4 == 0) red[rl * 4 + wn] = s;
                }
            }
            __syncthreads();
            if (t < TM) {
                float s = red[t * 4 + 0] + red[t * 4 + 1] + red[t * 4 + 2] + red[t * 4 + 3];
                g_partial[(rgBase + r_ * 64 + t) * NT2 + blockIdx.y] = s;
            }
            // reset accumulators for next row tile
            #pragma unroll
            for (int mi = 0; mi < 2; ++mi)
                #pragma unroll
                for (int ni = 0; ni < 4; ++ni)
                    #pragma unroll
                    for (int c = 0; c < 4; ++c) acc[mi][ni][c] = 0;
        }
    }
}

// ------- fused per-row: target dot + margin fixup + logsumexp + loss + mean ---
__global__ void row_kernel(const float* __restrict__ input,
                           const void*  __restrict__ label,
                           const float* __restrict__ weight,
                           float* __restrict__ out) {
    __shared__ float smf[4];
    __shared__ int   smi[4];
    __shared__ float smp[4];
    __shared__ int   isLast;
    const int r    = blockIdx.x;
    const int t    = threadIdx.x;
    const int lane = t & 31;
    const int wd   = t >> 5;
    const int lab  = get_label(label, r);

    const float4* xr = (const float4*)(input  + (long long)r   * DDIM);
    const float4* wr = (const float4*)(weight + (long long)lab * DDIM);
    float4 a = xr[t], b = wr[t];
    float s  = a.x * b.x + a.y * b.y + a.z * b.z + a.w * b.w;
    int   id = __dp4a(((const int*)(g_xq + ((long long)r   << 9)))[t],
                      ((const int*)(g_wq + ((long long)lab << 9)))[t], 0);
    float ps = 0.f;
    const float* pp = g_partial + (long long)r * NT2;
    for (int i = t; i < NT2; i += 128) ps += pp[i];

    #pragma unroll
    for (int off = 16; off >= 1; off >>= 1) {
        s  += __shfl_xor_sync(0xffffffffu, s, off);
        id += __shfl_xor_sync(0xffffffffu, id, off);
        ps += __shfl_xor_sync(0xffffffffu, ps, off);
    }
    if (lane == 0) { smf[wd] = s; smi[wd] = id; smp[wd] = ps; }
    __syncthreads();
    if (t == 0) {
        float st = smf[0] + smf[1] + smf[2] + smf[3];
        int   it = smi[0] + smi[1] + smi[2] + smi[3];
        float pt = smp[0] + smp[1] + smp[2] + smp[3];
        float tgt = SCALE * (st * g_rnx[r] * g_rwn[lab] - MARGIN);
        float fxr = g_fx[r] * (SCALE * L2E);
        float fq  = fxr * g_fw[lab];
        float tt  = (float)it * fq;
        float fix = ex2(tt - (SCALE * MARGIN * L2E)) - ex2(tt);
        g_rowloss[r] = logf(pt + fix) - tgt;
        __threadfence();
        unsigned v = atomicAdd(&g_ctr, 1u);
        isLast = (v == (unsigned)(BDIM - 1));
    }
    __syncthreads();
    if (isLast) {
        float v = g_rowloss[t] + g_rowloss[t + 128] + g_rowloss[t + 256] +
                  g_rowloss[t + 384] + g_rowloss[t + 512] + g_rowloss[t + 640] +
                  g_rowloss[t + 768] + g_rowloss[t + 896];
        #pragma unroll
        for (int off = 16; off >= 1; off >>= 1)
            v += __shfl_xor_sync(0xffffffffu, v, off);
        if (lane == 0) smf[wd] = v;
        __syncthreads();
        if (t == 0)
            out[0] = (smf[0] + smf[1] + smf[2] + smf[3]) * (1.0f / (float)BDIM);
    }
}

// ---------------- launch ------------------------------------------------------
extern "C" void kernel_launch(void* const* d_in, const int* in_sizes, int n_in,
                              void* d_out, int out_size) {
    const float* input  = (const float*)d_in[0];
    const void*  label  = d_in[1];
    const float* weight = (const float*)d_in[2];
    float* out = (float*)d_out;

    cudaFuncSetAttribute(tile_kernel, cudaFuncAttributeMaxDynamicSharedMemorySize, SMEM_TOTAL);

    detect_kernel<<<1, 256>>>(label);
    norm_quant_kernel<<<((BDIM + CDIM) * 32 + 255) / 256, 256>>>(input, weight);

    dim3 grid(NRG, NT2);
    tile_kernel<<<grid, 256, SMEM_TOTAL>>>();

    row_kernel<<<BDIM, 128>>>(input, label, weight, out);
}

// round 17
// speedup vs baseline: 2.0626x; 1.0478x over previous
#include <cuda_runtime.h>
#include <cuda_bf16.h>
#include <cstdint>
#include <math.h>

#define BDIM 1024
#define DDIM 512
#define CDIM 100000
#define SCALE 64.0f
#define MARGIN 0.35f
#define L2E 1.44269504f
#define TM 64
#define TN 128
#define NT2 ((CDIM + TN - 1) / TN)   // 782 class tiles
#define NRG 4                        // row groups (256 rows each)

// ---------------- static scratch ---------------------------------------------
__device__ int    g_is64;
__device__ unsigned g_ctr;
__device__ float  g_rnx[BDIM];
__device__ float  g_rwn[CDIM];
__device__ float  g_fx[BDIM];
__device__ float  g_fw[CDIM];
__device__ int8_t g_xq[BDIM * DDIM];
__device__ int8_t g_wq[(size_t)CDIM * DDIM];
__device__ float  g_partial4[(size_t)BDIM * NT2 * 4];   // [row][tile*4 + wn]
__device__ float  g_rowloss[BDIM];

// ---------------- helpers -----------------------------------------------------
__device__ __forceinline__ uint32_t smem_u32(const void* p) {
    uint32_t a;
    asm("{ .reg .u64 t; cvta.to.shared.u64 t, %1; cvt.u32.u64 %0, t; }" : "=r"(a) : "l"(p));
    return a;
}
__device__ __forceinline__ void cpa16(uint32_t dst, const void* src, int pred) {
    int sz = pred ? 16 : 0;
    asm volatile("cp.async.cg.shared.global [%0], [%1], 16, %2;" :: "r"(dst), "l"(src), "r"(sz));
}
#define CP_COMMIT() asm volatile("cp.async.commit_group;" ::: "memory")
#define CP_WAIT0()  asm volatile("cp.async.wait_group 0;" ::: "memory")

#define LDSM4(r0, r1, r2, r3, a) \
    asm volatile("ldmatrix.sync.aligned.m8n8.x4.shared.b16 {%0,%1,%2,%3}, [%4];" \
                 : "=r"(r0), "=r"(r1), "=r"(r2), "=r"(r3) : "r"(a))

#define IMMA16832(d, a, b) \
    asm volatile("mma.sync.aligned.m16n8k32.row.col.s32.s8.s8.s32 " \
                 "{%0,%1,%2,%3}, {%4,%5,%6,%7}, {%8,%9}, {%0,%1,%2,%3};" \
                 : "+r"((d)[0]), "+r"((d)[1]), "+r"((d)[2]), "+r"((d)[3]) \
                 : "r"((a)[0]), "r"((a)[1]), "r"((a)[2]), "r"((a)[3]), "r"((b)[0]), "r"((b)[1]))

__device__ __forceinline__ float ex2(float tt) {
    float r;
    asm("ex2.approx.f32 %0, %1;" : "=f"(r) : "f"(tt));
    return r;
}

// ---------------- label dtype ------------------------------------------------
__device__ __forceinline__ int get_label(const void* p, int i) {
    if (g_is64) return (int)((const long long*)p)[i];
    return ((const int*)p)[i];
}
__global__ void detect_kernel(const void* __restrict__ lab) {
    __shared__ int ok;
    if (threadIdx.x == 0) { ok = 1; g_ctr = 0u; }
    __syncthreads();
    const long long* q = (const long long*)lab;
    for (int i = threadIdx.x; i < BDIM / 2; i += blockDim.x) {
        long long v = q[i];
        if (v < 0 || v >= (long long)CDIM) ok = 0;
    }
    __syncthreads();
    if (threadIdx.x == 0) g_is64 = ok;
}

// ------- normalize + quantize BOTH tensors in one grid ------------------------
__global__ void norm_quant_kernel(const float* __restrict__ input,
                                  const float* __restrict__ weight) {
    int w    = (blockIdx.x * blockDim.x + threadIdx.x) >> 5;
    int lane = threadIdx.x & 31;
    if (w >= BDIM + CDIM) return;
    const int which = (w >= BDIM);
    const int row   = which ? (w - BDIM) : w;
    const float* p  = which ? weight : input;
    const float4* pr = (const float4*)(p + (long long)row * DDIM);
    float4 v[4];
    float ss = 0.f, ma = 0.f;
    #pragma unroll
    for (int j = 0; j < 4; ++j) {
        v[j] = pr[j * 32 + lane];
        ss += v[j].x * v[j].x + v[j].y * v[j].y + v[j].z * v[j].z + v[j].w * v[j].w;
        ma = fmaxf(ma, fmaxf(fmaxf(fabsf(v[j].x), fabsf(v[j].y)),
                             fmaxf(fabsf(v[j].z), fabsf(v[j].w))));
    }
    #pragma unroll
    for (int off = 16; off >= 1; off >>= 1) {
        ss += __shfl_xor_sync(0xffffffffu, ss, off);
        ma = fmaxf(ma, __shfl_xor_sync(0xffffffffu, ma, off));
    }
    float r  = 1.0f / fmaxf(sqrtf(ss), 1e-12f);
    float qs = 127.0f / fmaxf(ma, 1e-30f);
    float f  = ma * r * (1.0f / 127.0f);
    if (lane == 0) {
        if (which) { g_rwn[row] = r; g_fw[row] = f; }
        else       { g_rnx[row] = r; g_fx[row] = f; }
    }
    uint32_t* dst = (uint32_t*)((which ? g_wq : g_xq) + (long long)row * DDIM);
    #pragma unroll
    for (int j = 0; j < 4; ++j) {
        int q0 = __float2int_rn(v[j].x * qs);
        int q1 = __float2int_rn(v[j].y * qs);
        int q2 = __float2int_rn(v[j].z * qs);
        int q3 = __float2int_rn(v[j].w * qs);
        uint32_t pk = (uint32_t)(q0 & 0xff) | ((uint32_t)(q1 & 0xff) << 8) |
                      ((uint32_t)(q2 & 0xff) << 16) | ((uint32_t)(q3 & 0xff) << 24);
        dst[j * 32 + lane] = pk;
    }
}

// smem layout:
//   B: 4 chunk regions @ 0,     each 128 rows x 144 B = 18432 -> 73728
//   A: 4 slots         @ 73728, each 64 rows x 144 B  = 9216  -> 36864
//   qx @110592 (256 floats), qw @111616 (128 floats)
#define SM_A    73728u
#define SM_QX   110592
#define SM_QW   111616
#define SMEM_TOTAL 112128

// ---------------- B-resident multi-row-tile IMMA kernel -----------------------
__global__ __launch_bounds__(256, 2) void tile_kernel() {
    extern __shared__ char smem[];
    const int t    = threadIdx.x;
    const int wid  = t >> 5;
    const int lane = t & 31;
    const int wm   = wid >> 2;
    const int wn   = wid & 3;
    const int rgBase  = blockIdx.x * 256;
    const int colBase = blockIdx.y * TN;
    const uint32_t sb = smem_u32(smem);
    float* qxS = (float*)(smem + SM_QX);
    float* qwS = (float*)(smem + SM_QW);

    qxS[t] = g_fx[rgBase + t] * (SCALE * L2E);
    if (t < TN) {
        int cg = colBase + t;
        qwS[t] = (cg < CDIM) ? g_fw[cg] : 0.f;
    }

    // ---- B loader: all 4 K-chunks, one commit group (64 KB) ----
    const int brow = t >> 1;
    const int bsec = (t & 1) * 4;
    int cgB = colBase + brow;
    int bpred = cgB < CDIM;
    const int8_t* bgp = g_wq + ((long long)(bpred ? cgB : 0) << 9) + (bsec << 4);
    const uint32_t bdst = sb + brow * 144 + bsec * 16;
    #pragma unroll
    for (int c = 0; c < 4; ++c) {
        #pragma unroll
        for (int s = 0; s < 4; ++s)
            cpa16(bdst + c * 18432u + s * 16, bgp + (c << 7) + s * 16, bpred);
    }
    CP_COMMIT();

    // ---- A loader (tile i: r = i>>2, kc = i&3; slot = i&3 of 4) ----
    const int arow = t >> 2;
    const int asec = (t & 3) * 2;
    const uint32_t adst0 = sb + SM_A + arow * 144 + asec * 16;
    #define LOAD_A(i) do {                                                     \
        int r_ = (i) >> 2, kc_ = (i) & 3;                                      \
        const int8_t* as = g_xq + ((long long)(rgBase + r_ * 64 + arow) << 9)  \
                           + (kc_ << 7) + (asec << 4);                         \
        uint32_t ad = adst0 + (uint32_t)((i) & 3) * 9216u;                     \
        cpa16(ad,      as,      1);                                            \
        cpa16(ad + 16, as + 16, 1);                                            \
    } while (0)

    LOAD_A(0);
    LOAD_A(1);
    CP_COMMIT();                      // pair P(0)

    // barrier: qxS/qwS written by thread subsets, read by all warps below
    __syncthreads();

    const uint32_t aAddrBase = sb + SM_A + (wm * 32 + (lane & 15)) * 144 + (lane >> 4) * 16;
    const int g = lane >> 3;
    const uint32_t bAddrBase = sb
        + (wn * 32 + ((g >> 1) << 3) + (lane & 7)) * 144 + (g & 1) * 16;

    const bool fullTile = (colBase + TN) <= CDIM;
    const int groupID = lane >> 2;
    const int tid4    = lane & 3;
    float qwr[8];
    #pragma unroll
    for (int ni = 0; ni < 4; ++ni) {
        qwr[2 * ni]     = qwS[wn * 32 + ni * 8 + tid4 * 2];
        qwr[2 * ni + 1] = qwS[wn * 32 + ni * 8 + tid4 * 2 + 1];
    }

    int acc[2][4][4];
    #pragma unroll
    for (int mi = 0; mi < 2; ++mi)
        #pragma unroll
        for (int ni = 0; ni < 4; ++ni)
            #pragma unroll
            for (int c = 0; c < 4; ++c) acc[mi][ni][c] = 0;

    // ---- mainloop: pair-granular pipeline, ONE wait + ONE barrier per 2 iters
    #pragma unroll 1
    for (int i = 0; i < 16; i += 2) {
        CP_WAIT0();                   // P(i) done (B also drains on first pass)
        __syncthreads();              // all warps finished slots (i+2)&3,(i+3)&3
        if (i < 14) {
            LOAD_A(i + 2);
            LOAD_A(i + 3);
            CP_COMMIT();              // pair P(i+2); fetches during compute below
        }
        #pragma unroll
        for (int sub = 0; sub < 2; ++sub) {
            const int it = i + sub;
            const uint32_t aB = aAddrBase + (uint32_t)(it & 3) * 9216u;
            const uint32_t bB = bAddrBase + (uint32_t)(it & 3) * 18432u;
            #pragma unroll
            for (int ks = 0; ks < 4; ++ks) {
                uint32_t afr[2][4];
                uint32_t bfr[4][2];
                #pragma unroll
                for (int mi = 0; mi < 2; ++mi)
                    LDSM4(afr[mi][0], afr[mi][1], afr[mi][2], afr[mi][3],
                          aB + mi * 16 * 144 + ks * 32);
                #pragma unroll
                for (int p = 0; p < 2; ++p)
                    LDSM4(bfr[2 * p][0], bfr[2 * p][1], bfr[2 * p + 1][0], bfr[2 * p + 1][1],
                          bB + p * 16 * 144 + ks * 32);
                #pragma unroll
                for (int mi = 0; mi < 2; ++mi)
                    #pragma unroll
                    for (int ni = 0; ni < 4; ++ni)
                        IMMA16832(acc[mi][ni], afr[mi], bfr[ni]);
            }
        }

        if ((i & 2) != 0) {
            // ---- epilogue for row tile r_ = (i+1)>>2 : no barrier, no smem ----
            const int r_ = (i + 1) >> 2;
            #pragma unroll
            for (int mi = 0; mi < 2; ++mi) {
                #pragma unroll
                for (int half = 0; half < 2; ++half) {
                    const int rl  = wm * 32 + mi * 16 + groupID + half * 8;
                    const float fxr = qxS[r_ * 64 + rl];
                    float fq[8];
                    #pragma unroll
                    for (int c = 0; c < 8; ++c) fq[c] = fxr * qwr[c];
                    float s0 = 0.f, s1 = 0.f;
                    if (fullTile) {
                        #pragma unroll
                        for (int ni = 0; ni < 4; ++ni) {
                            float fa0 = (float)acc[mi][ni][half * 2 + 0];
                            float fa1 = (float)acc[mi][ni][half * 2 + 1];
                            s0 += ex2(fa0 * fq[2 * ni]);
                            s1 += ex2(fa1 * fq[2 * ni + 1]);
                        }
                    } else {
                        #pragma unroll
                        for (int ni = 0; ni < 4; ++ni) {
                            #pragma unroll
                            for (int cc = 0; cc < 2; ++cc) {
                                const int col = colBase + wn * 32 + ni * 8 + tid4 * 2 + cc;
                                if (col < CDIM) {
                                    float fa = (float)acc[mi][ni][half * 2 + cc];
                                    s0 += ex2(fa * fq[2 * ni + cc]);
                                }
                            }
                        }
                    }
                    float s = s0 + s1;
                    s += __shfl_xor_sync(0xffffffffu, s, 1);
                    s += __shfl_xor_sync(0xffffffffu, s, 2);
                    if (tid4 == 0)
                        g_partial4[(size_t)(rgBase + r_ * 64 + rl) * (NT2 * 4)
                                   + blockIdx.y * 4 + wn] = s;
                }
            }
            // reset accumulators for next row tile
            #pragma unroll
            for (int mi = 0; mi < 2; ++mi)
                #pragma unroll
                for (int ni = 0; ni < 4; ++ni)
                    #pragma unroll
                    for (int c = 0; c < 4; ++c) acc[mi][ni][c] = 0;
        }
    }
}

// ------- fused per-row: target dot + margin fixup + logsumexp + loss + mean ---
__global__ void row_kernel(const float* __restrict__ input,
                           const void*  __restrict__ label,
                           const float* __restrict__ weight,
                           float* __restrict__ out) {
    __shared__ float smf[4];
    __shared__ int   smi[4];
    __shared__ float smp[4];
    __shared__ int   isLast;
    const int r    = blockIdx.x;
    const int t    = threadIdx.x;
    const int lane = t & 31;
    const int wd   = t >> 5;
    const int lab  = get_label(label, r);

    const float4* xr = (const float4*)(input  + (long long)r   * DDIM);
    const float4* wr = (const float4*)(weight + (long long)lab * DDIM);
    float4 a = xr[t], b = wr[t];
    float s  = a.x * b.x + a.y * b.y + a.z * b.z + a.w * b.w;
    int   id = __dp4a(((const int*)(g_xq + ((long long)r   << 9)))[t],
                      ((const int*)(g_wq + ((long long)lab << 9)))[t], 0);
    float ps = 0.f;
    const float* pp = g_partial4 + (size_t)r * (NT2 * 4);
    for (int i = t; i < NT2 * 4; i += 128) ps += pp[i];

    #pragma unroll
    for (int off = 16; off >= 1; off >>= 1) {
        s  += __shfl_xor_sync(0xffffffffu, s, off);
        id += __shfl_xor_sync(0xffffffffu, id, off);
        ps += __shfl_xor_sync(0xffffffffu, ps, off);
    }
    if (lane == 0) { smf[wd] = s; smi[wd] = id; smp[wd] = ps; }
    __syncthreads();
    if (t == 0) {
        float st = smf[0] + smf[1] + smf[2] + smf[3];
        int   it = smi[0] + smi[1] + smi[2] + smi[3];
        float pt = smp[0] + smp[1] + smp[2] + smp[3];
        float tgt = SCALE * (st * g_rnx[r] * g_rwn[lab] - MARGIN);
        float fxr = g_fx[r] * (SCALE * L2E);
        float fq  = fxr * g_fw[lab];
        float tt  = (float)it * fq;
        float fix = ex2(tt - (SCALE * MARGIN * L2E)) - ex2(tt);
        g_rowloss[r] = logf(pt + fix) - tgt;
        __threadfence();
        unsigned v = atomicAdd(&g_ctr, 1u);
        isLast = (v == (unsigned)(BDIM - 1));
    }
    __syncthreads();
    if (isLast) {
        float v = g_rowloss[t] + g_rowloss[t + 128] + g_rowloss[t + 256] +
                  g_rowloss[t + 384] + g_rowloss[t + 512] + g_rowloss[t + 640] +
                  g_rowloss[t + 768] + g_rowloss[t + 896];
        #pragma unroll
        for (int off = 16; off >= 1; off >>= 1)
            v += __shfl_xor_sync(0xffffffffu, v, off);
        if (lane == 0) smf[wd] = v;
        __syncthreads();
        if (t == 0)
            out[0] = (smf[0] + smf[1] + smf[2] + smf[3]) * (1.0f / (float)BDIM);
    }
}

// ---------------- launch ------------------------------------------------------
extern "C" void kernel_launch(void* const* d_in, const int* in_sizes, int n_in,
                              void* d_out, int out_size) {
    const float* input  = (const float*)d_in[0];
    const void*  label  = d_in[1];
    const float* weight = (const float*)d_in[2];
    float* out = (float*)d_out;

    cudaFuncSetAttribute(tile_kernel, cudaFuncAttributeMaxDynamicSharedMemorySize, SMEM_TOTAL);

    detect_kernel<<<1, 256>>>(label);
    norm_quant_kernel<<<((BDIM + CDIM) * 32 + 255) / 256, 256>>>(input, weight);

    dim3 grid(NRG, NT2);
    tile_kernel<<<grid, 256, SMEM_TOTAL>>>();

    row_kernel<<<BDIM, 128>>>(input, label, weight, out);
}